// round 11
// baseline (speedup 1.0000x reference)
#include <cuda_runtime.h>
#include <cuda_bf16.h>
#include <stdint.h>
#include <math.h>

#define T    512
#define H    2048
#define II   1024
#define E    64
#define KSEL 8

#define BM   64
#define BK   32
#define PADK 40        // bf16 A row stride: 40 elems = 80B (ldmatrix conflict-free)
#define NSTAGE 3

// stage byte layout (both kernels): A hi/lo bf16 (64x40), B fp32 rows 160B
#define A_HI   0
#define A_LO   5120
#define B0_F32 10240   // down: Wd 128 rows x 160B ; gateup: Wg 64 rows
#define B1_F32 20480   // gateup: Wu 64 rows
#define STG_BYTES 30720
#define META_OFF (NSTAGE * STG_BYTES)    // 92160
#define SMEM_DYN (META_OFF + 1024)

// -------- device-global scratch (no allocations allowed) --------
__device__ int   g_cnt[E];
__device__ int   g_off[E];
__device__ int   g_tok[E * T];
__device__ float g_prob[E * T];
__device__ __nv_bfloat16 g_act_h[(size_t)T * KSEL * II];
__device__ __nv_bfloat16 g_act_l[(size_t)T * KSEL * II];
__device__ __nv_bfloat16 g_x_h[(size_t)T * H];
__device__ __nv_bfloat16 g_x_l[(size_t)T * H];

// ======================= helpers =======================
__device__ __forceinline__ uint32_t smem_u32(const void* p) {
    uint32_t a;
    asm("{ .reg .u64 t; cvta.to.shared.u64 t, %1; cvt.u32.u64 %0, t; }" : "=r"(a) : "l"(p));
    return a;
}
#define CP16(dst, src) \
    asm volatile("cp.async.cg.shared.global [%0], [%1], 16;" :: "r"((uint32_t)(dst)), "l"(src) : "memory")
#define CP_COMMIT()  asm volatile("cp.async.commit_group;" ::: "memory")
#define CP_WAIT_1()  asm volatile("cp.async.wait_group 1;" ::: "memory")
#define CP_WAIT_0()  asm volatile("cp.async.wait_group 0;" ::: "memory")

__device__ __forceinline__ void ldm_x4(uint32_t r[4], uint32_t addr) {
    asm volatile("ldmatrix.sync.aligned.m8n8.x4.shared.b16 {%0,%1,%2,%3}, [%4];"
                 : "=r"(r[0]), "=r"(r[1]), "=r"(r[2]), "=r"(r[3]) : "r"(addr));
}
__device__ __forceinline__ void mma_bf16(float d[4], const uint32_t a[4], uint32_t b0, uint32_t b1) {
    asm volatile("mma.sync.aligned.m16n8k16.row.col.f32.bf16.bf16.f32 "
                 "{%0,%1,%2,%3}, {%4,%5,%6,%7}, {%8,%9}, {%0,%1,%2,%3};"
                 : "+f"(d[0]), "+f"(d[1]), "+f"(d[2]), "+f"(d[3])
                 : "r"(a[0]), "r"(a[1]), "r"(a[2]), "r"(a[3]), "r"(b0), "r"(b1));
}
// split a float2 into packed bf16x2 hi and lo
__device__ __forceinline__ void split2(float2 f, uint32_t& hi, uint32_t& lo) {
    __nv_bfloat16 h0 = __float2bfloat16(f.x), h1 = __float2bfloat16(f.y);
    __nv_bfloat16 l0 = __float2bfloat16(f.x - __bfloat162float(h0));
    __nv_bfloat16 l1 = __float2bfloat16(f.y - __bfloat162float(h1));
    hi = (uint32_t)__bfloat16_as_ushort(h0) | ((uint32_t)__bfloat16_as_ushort(h1) << 16);
    lo = (uint32_t)__bfloat16_as_ushort(l0) | ((uint32_t)__bfloat16_as_ushort(l1) << 16);
}

// ======================= x pre-split =======================
__global__ void xsplit_kernel(const float* __restrict__ x)
{
    const int i = blockIdx.x * 256 + threadIdx.x;       // T*H/4 float4s
    float4 v = ((const float4*)x)[i];
    uint32_t h01, l01, h23, l23;
    split2(make_float2(v.x, v.y), h01, l01);
    split2(make_float2(v.z, v.w), h23, l23);
    ((uint2*)g_x_h)[i] = make_uint2(h01, h23);
    ((uint2*)g_x_l)[i] = make_uint2(l01, l23);
}

// ======================= gating =======================
__global__ void gate_kernel(const float* __restrict__ x,
                            const float* __restrict__ Wgate)
{
    __shared__ float sx[H];
    __shared__ float slog[E];
    __shared__ int   s_ids[KSEL];
    __shared__ float s_p[KSEL];

    const int t = blockIdx.x, tid = threadIdx.x;
    for (int i = tid; i < H; i += blockDim.x) sx[i] = x[(size_t)t * H + i];
    __syncthreads();

    const int w = tid >> 5, lane = tid & 31;
    for (int j = 0; j < 8; j++) {
        const int e = w * 8 + j;
        const float* wr = Wgate + (size_t)e * H;
        float s = 0.f;
        for (int h = lane; h < H; h += 32) s += sx[h] * wr[h];
        #pragma unroll
        for (int o = 16; o > 0; o >>= 1) s += __shfl_xor_sync(0xffffffffu, s, o);
        if (lane == 0) slog[e] = s;
    }
    __syncthreads();

    if (tid == 0) {
        float vals[KSEL]; int ids[KSEL];
        for (int j = 0; j < KSEL; j++) {
            float best = -1e30f; int bi = 0;
            for (int e = 0; e < E; e++)
                if (slog[e] > best) { best = slog[e]; bi = e; }
            vals[j] = best; ids[j] = bi; slog[bi] = -1e30f;
        }
        const float m = vals[0];
        float sum = 0.f;
        for (int j = 0; j < KSEL; j++) { vals[j] = expf(vals[j] - m); sum += vals[j]; }
        const float inv = 1.f / sum;
        for (int j = 0; j < KSEL; j++) { s_ids[j] = ids[j]; s_p[j] = vals[j] * inv; }
    }
    __syncthreads();

    if (tid < KSEL) {
        const int e = s_ids[tid];
        const int pos = atomicAdd(&g_cnt[e], 1);
        g_tok[e * T + pos]  = t;
        g_prob[e * T + pos] = s_p[tid];
    }
}

__global__ void scan_kernel()
{
    if (threadIdx.x == 0) {
        int s = 0;
        for (int e = 0; e < E; e++) { g_off[e] = s; s += g_cnt[e]; }
    }
}

// ======================= gate/up: cp.async pipeline + mma.sync + SwiGLU =======================
// CTA: 64 tokens x 64 i x {Wg,Wu}. 8 warps 2m x 4n, warp 32m x 16i x 2 mats.
__global__ __launch_bounds__(256, 2) void gateup_mma(const float* __restrict__ Wg,
                                                     const float* __restrict__ Wu)
{
    extern __shared__ __align__(16) char smraw[];

    const int e   = blockIdx.z;
    const int cnt = g_cnt[e];
    const int m0  = blockIdx.y * BM;
    if (m0 >= cnt) return;
    const int i0   = blockIdx.x * 64;
    const int base = g_off[e];
    const int tid = threadIdx.x, wid = tid >> 5, lane = tid & 31;
    const uint32_t sb = smem_u32(smraw);

    int*   stok = (int*)(smraw + META_OFF);
    float* sp   = (float*)(smraw + META_OFF + 256);
    if (tid < BM) {
        const int mm = min(m0 + tid, cnt - 1);
        stok[tid] = g_tok[e * T + mm];
        sp[tid]   = (m0 + tid < cnt) ? g_prob[e * T + m0 + tid] : 0.f;
    }
    __syncthreads();

    const float* WgE = Wg + ((size_t)e * II + i0) * H;
    const float* WuE = Wu + ((size_t)e * II + i0) * H;
    const int NCH = H / BK;    // 64

    // ---- producer task geometry (all threads) ----
    const int ra  = (tid >> 2) & 63;           // A row 0..63
    const int sga = tid & 3;                   // A 16B segment
    const __nv_bfloat16* srcAh = g_x_h + (size_t)stok[ra] * H + sga * 8;
    const __nv_bfloat16* srcAl = g_x_l + (size_t)stok[ra] * H + sga * 8;
    const uint32_t dstA = (uint32_t)(ra * 80 + sga * 16);
    const int sgb = tid & 7;                   // B 16B segment
    const int rb0 = tid >> 3, rb1 = rb0 + 32;  // B rows
    const float* srcG[2] = { WgE + (size_t)rb0 * H + sgb * 4, WgE + (size_t)rb1 * H + sgb * 4 };
    const float* srcU[2] = { WuE + (size_t)rb0 * H + sgb * 4, WuE + (size_t)rb1 * H + sgb * 4 };
    const uint32_t dstB[2] = { (uint32_t)(rb0 * 160 + sgb * 16), (uint32_t)(rb1 * 160 + sgb * 16) };

    #define GU_FILL(s_, ch_) do {                                          \
        const uint32_t so = sb + (uint32_t)(s_) * STG_BYTES;                \
        const int k0 = (ch_) * BK;                                          \
        CP16(so + A_HI + dstA, srcAh + k0);                                 \
        CP16(so + A_LO + dstA, srcAl + k0);                                 \
        CP16(so + B0_F32 + dstB[0], srcG[0] + k0);                          \
        CP16(so + B0_F32 + dstB[1], srcG[1] + k0);                          \
        CP16(so + B1_F32 + dstB[0], srcU[0] + k0);                          \
        CP16(so + B1_F32 + dstB[1], srcU[1] + k0);                          \
        CP_COMMIT();                                                        \
    } while (0)

    GU_FILL(0, 0);
    GU_FILL(1, 1);

    // ---- consumer geometry ----
    const int wm = wid >> 2;   // 0..1
    const int wn = wid & 3;    // 0..3
    const uint32_t offA0 = (uint32_t)((wm * 32 + (lane & 15)) * PADK + ((lane >> 4) << 3)) * 2;
    const uint32_t offA1 = offA0 + 16 * PADK * 2;
    const int bcol = 2 * (lane & 3);

    float ag[2][2][4] = {}, au[2][2][4] = {};

    for (int ch = 0; ch < NCH; ch++) {
        if (ch < NCH - 1) CP_WAIT_1(); else CP_WAIT_0();
        __syncthreads();
        if (ch + 2 < NCH) GU_FILL((ch + 2) % NSTAGE, ch + 2);

        const int st = ch % NSTAGE;
        const uint32_t sbase = sb + (uint32_t)st * STG_BYTES;
        const float* Gst = (const float*)(smraw + st * STG_BYTES + B0_F32);
        const float* Ust = (const float*)(smraw + st * STG_BYTES + B1_F32);

        #pragma unroll
        for (int k16 = 0; k16 < BK; k16 += 16) {
            const uint32_t kb = (uint32_t)k16 * 2;
            uint32_t ah[2][4], al[2][4];
            ldm_x4(ah[0], sbase + A_HI + offA0 + kb);
            ldm_x4(al[0], sbase + A_LO + offA0 + kb);
            ldm_x4(ah[1], sbase + A_HI + offA1 + kb);
            ldm_x4(al[1], sbase + A_LO + offA1 + kb);
            #pragma unroll
            for (int it = 0; it < 2; it++) {
                const int row = wn * 16 + it * 8 + (lane >> 2);
                float2 f0 = *(const float2*)(Gst + row * 40 + k16 + bcol);
                float2 f1 = *(const float2*)(Gst + row * 40 + k16 + bcol + 8);
                uint32_t gh0, gl0, gh1, gl1;
                split2(f0, gh0, gl0); split2(f1, gh1, gl1);
                f0 = *(const float2*)(Ust + row * 40 + k16 + bcol);
                f1 = *(const float2*)(Ust + row * 40 + k16 + bcol + 8);
                uint32_t uh0, ul0, uh1, ul1;
                split2(f0, uh0, ul0); split2(f1, uh1, ul1);
                #pragma unroll
                for (int mt = 0; mt < 2; mt++) {
                    mma_bf16(ag[mt][it], ah[mt], gh0, gh1);
                    mma_bf16(ag[mt][it], ah[mt], gl0, gl1);
                    mma_bf16(ag[mt][it], al[mt], gh0, gh1);
                    mma_bf16(au[mt][it], ah[mt], uh0, uh1);
                    mma_bf16(au[mt][it], ah[mt], ul0, ul1);
                    mma_bf16(au[mt][it], al[mt], uh0, uh1);
                }
            }
        }
    }

    // epilogue: silu(hg)*hu*p -> g_act hi/lo planes
    #pragma unroll
    for (int mt = 0; mt < 2; mt++) {
        #pragma unroll
        for (int it = 0; it < 2; it++) {
            const int c  = i0 + wn * 16 + it * 8 + (lane & 3) * 2;
            const int r0 = wm * 32 + mt * 16 + (lane >> 2);
            #pragma unroll
            for (int hf = 0; hf < 2; hf++) {
                const int r = r0 + hf * 8;
                if (m0 + r < cnt) {
                    const float p = sp[r];
                    const float hg0 = ag[mt][it][hf * 2 + 0], hu0 = au[mt][it][hf * 2 + 0];
                    const float hg1 = ag[mt][it][hf * 2 + 1], hu1 = au[mt][it][hf * 2 + 1];
                    float2 v;
                    v.x = hg0 / (1.f + expf(-hg0)) * hu0 * p;
                    v.y = hg1 / (1.f + expf(-hg1)) * hu1 * p;
                    uint32_t hi, lo;
                    split2(v, hi, lo);
                    const size_t off = (size_t)(base + m0 + r) * II + c;
                    *(uint32_t*)(g_act_h + off) = hi;
                    *(uint32_t*)(g_act_l + off) = lo;
                }
            }
        }
    }
    #undef GU_FILL
}

// ======================= down: cp.async pipeline + mma.sync + scatter =======================
// CTA: 64 rows x 128 h-cols. 8 warps 2m x 4n, warp 32m x 32n.
__global__ __launch_bounds__(256, 2) void down_mma(const float* __restrict__ Wd,
                                                   float* __restrict__ out)
{
    extern __shared__ __align__(16) char smraw[];

    const int e   = blockIdx.z;
    const int cnt = g_cnt[e];
    const int m0  = blockIdx.y * BM;
    if (m0 >= cnt) return;
    const int n0   = blockIdx.x * 128;
    const int base = g_off[e];
    const int tid = threadIdx.x, wid = tid >> 5, lane = tid & 31;
    const uint32_t sb = smem_u32(smraw);

    int* stok = (int*)(smraw + META_OFF);
    int* srow = (int*)(smraw + META_OFF + 256);
    if (tid < BM) {
        const int mm = min(m0 + tid, cnt - 1);
        stok[tid] = g_tok[e * T + mm];
        srow[tid] = base + mm;
    }
    __syncthreads();

    const float* WdE = Wd + ((size_t)e * H + n0) * II;
    const int NCH = II / BK;   // 32

    // ---- producer task geometry ----
    const int ra  = (tid >> 2) & 63;
    const int sga = tid & 3;
    const __nv_bfloat16* srcAh = g_act_h + (size_t)srow[ra] * II + sga * 8;
    const __nv_bfloat16* srcAl = g_act_l + (size_t)srow[ra] * II + sga * 8;
    const uint32_t dstA = (uint32_t)(ra * 80 + sga * 16);
    const int sgb = tid & 7;
    const int rb = tid >> 3;                    // 0..31
    const float* srcB[4];
    uint32_t dstB[4];
    #pragma unroll
    for (int j = 0; j < 4; j++) {
        const int r = rb + j * 32;              // 0..127
        srcB[j] = WdE + (size_t)r * II + sgb * 4;
        dstB[j] = (uint32_t)(r * 160 + sgb * 16);
    }

    #define DN_FILL(s_, ch_) do {                                          \
        const uint32_t so = sb + (uint32_t)(s_) * STG_BYTES;                \
        const int k0 = (ch_) * BK;                                          \
        CP16(so + A_HI + dstA, srcAh + k0);                                 \
        CP16(so + A_LO + dstA, srcAl + k0);                                 \
        CP16(so + B0_F32 + dstB[0], srcB[0] + k0);                          \
        CP16(so + B0_F32 + dstB[1], srcB[1] + k0);                          \
        CP16(so + B0_F32 + dstB[2], srcB[2] + k0);                          \
        CP16(so + B0_F32 + dstB[3], srcB[3] + k0);                          \
        CP_COMMIT();                                                        \
    } while (0)

    DN_FILL(0, 0);
    DN_FILL(1, 1);

    // ---- consumer geometry ----
    const int wm = wid >> 2;   // 0..1
    const int wn = wid & 3;    // 0..3
    const uint32_t offA0 = (uint32_t)((wm * 32 + (lane & 15)) * PADK + ((lane >> 4) << 3)) * 2;
    const uint32_t offA1 = offA0 + 16 * PADK * 2;
    const int bcol = 2 * (lane & 3);

    float acc[2][4][4] = {};

    for (int ch = 0; ch < NCH; ch++) {
        if (ch < NCH - 1) CP_WAIT_1(); else CP_WAIT_0();
        __syncthreads();
        if (ch + 2 < NCH) DN_FILL((ch + 2) % NSTAGE, ch + 2);

        const int st = ch % NSTAGE;
        const uint32_t sbase = sb + (uint32_t)st * STG_BYTES;
        const float* Bst = (const float*)(smraw + st * STG_BYTES + B0_F32);

        #pragma unroll
        for (int k16 = 0; k16 < BK; k16 += 16) {
            const uint32_t kb = (uint32_t)k16 * 2;
            uint32_t ah[2][4], al[2][4];
            ldm_x4(ah[0], sbase + A_HI + offA0 + kb);
            ldm_x4(al[0], sbase + A_LO + offA0 + kb);
            ldm_x4(ah[1], sbase + A_HI + offA1 + kb);
            ldm_x4(al[1], sbase + A_LO + offA1 + kb);
            #pragma unroll
            for (int nt = 0; nt < 4; nt++) {
                const int row = wn * 32 + nt * 8 + (lane >> 2);
                float2 f0 = *(const float2*)(Bst + row * 40 + k16 + bcol);
                float2 f1 = *(const float2*)(Bst + row * 40 + k16 + bcol + 8);
                uint32_t bh0, bl0, bh1, bl1;
                split2(f0, bh0, bl0); split2(f1, bh1, bl1);
                #pragma unroll
                for (int mt = 0; mt < 2; mt++) {
                    mma_bf16(acc[mt][nt], ah[mt], bh0, bh1);
                    mma_bf16(acc[mt][nt], ah[mt], bl0, bl1);
                    mma_bf16(acc[mt][nt], al[mt], bh0, bh1);
                }
            }
        }
    }

    // epilogue: atomic scatter into out
    #pragma unroll
    for (int mt = 0; mt < 2; mt++) {
        #pragma unroll
        for (int nt = 0; nt < 4; nt++) {
            const int c  = n0 + wn * 32 + nt * 8 + (lane & 3) * 2;
            const int r0 = wm * 32 + mt * 16 + (lane >> 2);
            #pragma unroll
            for (int hf = 0; hf < 2; hf++) {
                const int r = r0 + hf * 8;
                if (m0 + r < cnt) {
                    float* orow = out + (size_t)stok[r] * H + c;
                    atomicAdd(&orow[0], acc[mt][nt][hf * 2 + 0]);
                    atomicAdd(&orow[1], acc[mt][nt][hf * 2 + 1]);
                }
            }
        }
    }
    #undef DN_FILL
}

// ======================= launch =======================
extern "C" void kernel_launch(void* const* d_in, const int* in_sizes, int n_in,
                              void* d_out, int out_size)
{
    const float* x     = (const float*)d_in[0];
    const float* Wg    = (const float*)d_in[1];
    const float* Wu    = (const float*)d_in[2];
    const float* Wd    = (const float*)d_in[3];
    const float* Wgate = (const float*)d_in[4];
    float* out = (float*)d_out;

    cudaFuncSetAttribute(gateup_mma, cudaFuncAttributeMaxDynamicSharedMemorySize, SMEM_DYN);
    cudaFuncSetAttribute(down_mma,   cudaFuncAttributeMaxDynamicSharedMemorySize, SMEM_DYN);

    void* cnt_ptr = nullptr;
    cudaGetSymbolAddress(&cnt_ptr, g_cnt);
    cudaMemsetAsync(cnt_ptr, 0, E * sizeof(int));
    cudaMemsetAsync(d_out, 0, (size_t)T * H * sizeof(float));

    xsplit_kernel<<<(T * H / 4) / 256, 256>>>(x);
    gate_kernel<<<T, 256>>>(x, Wgate);
    scan_kernel<<<1, 32>>>();

    dim3 g1(II / 64, T / BM, E);     // 16 x 8 x 64
    gateup_mma<<<g1, 256, SMEM_DYN>>>(Wg, Wu);

    dim3 g2(H / 128, T / BM, E);     // 16 x 8 x 64
    down_mma<<<g2, 256, SMEM_DYN>>>(Wd, out);
}

// round 12
// speedup vs baseline: 1.4658x; 1.4658x over previous
#include <cuda_runtime.h>
#include <cuda_fp16.h>
#include <stdint.h>
#include <math.h>

#define T    512
#define H    2048
#define II   1024
#define E    64
#define KSEL 8

#define BM   64
#define BK   32
#define PADK 40                      // padded k-stride (fp16 elems): 80B, ldmatrix conflict-free

// stage = 10240 fp16 elems = 20480 B; two stages.
#define STG_ELEMS 10240
#define META_OFF  (2 * STG_ELEMS * 2)          // 40960 B
#define SMEM_DYN  (META_OFF + 1024)

// gateup regions (elem offsets within a stage): A hi/lo 64x40, G 64x40, U 64x40
#define GA_HI 0
#define GA_LO 2560
#define GG    5120
#define GU    7680
// down regions: A hi/lo 64x40, B 128x40
#define DA_HI 0
#define DA_LO 2560
#define DB    5120

// -------- device-global scratch (no allocations allowed) --------
__device__ int   g_cnt[E];
__device__ int   g_off[E];
__device__ int   g_tok[E * T];
__device__ float g_prob[E * T];
__device__ float g_act[(size_t)T * KSEL * II];

// ======================= helpers =======================
__device__ __forceinline__ uint32_t smem_u32(const void* p) {
    uint32_t a;
    asm("{ .reg .u64 t; cvta.to.shared.u64 t, %1; cvt.u32.u64 %0, t; }" : "=r"(a) : "l"(p));
    return a;
}

__device__ __forceinline__ void ldm_x4(uint32_t r[4], uint32_t addr) {
    asm volatile("ldmatrix.sync.aligned.m8n8.x4.shared.b16 {%0,%1,%2,%3}, [%4];"
                 : "=r"(r[0]), "=r"(r[1]), "=r"(r[2]), "=r"(r[3]) : "r"(addr));
}
__device__ __forceinline__ void mma_f16(float d[4], const uint32_t a[4], uint32_t b0, uint32_t b1) {
    asm volatile("mma.sync.aligned.m16n8k16.row.col.f32.f16.f16.f32 "
                 "{%0,%1,%2,%3}, {%4,%5,%6,%7}, {%8,%9}, {%0,%1,%2,%3};"
                 : "+f"(d[0]), "+f"(d[1]), "+f"(d[2]), "+f"(d[3])
                 : "r"(a[0]), "r"(a[1]), "r"(a[2]), "r"(a[3]), "r"(b0), "r"(b1));
}

// fp32x4 -> fp16x4 single plane (8 B)
__device__ __forceinline__ uint2 cvt4_f16(float4 v) {
    __half2 a = __floats2half2_rn(v.x, v.y);
    __half2 b = __floats2half2_rn(v.z, v.w);
    uint2 r;
    r.x = *(uint32_t*)&a;
    r.y = *(uint32_t*)&b;
    return r;
}
// fp32x4 -> fp16 hi/lo planes (8 B each)
__device__ __forceinline__ void split_sts_f16(__half* hi, __half* lo, float4 v) {
    __half2 h01 = __floats2half2_rn(v.x, v.y);
    __half2 h23 = __floats2half2_rn(v.z, v.w);
    float2 f01 = __half22float2(h01), f23 = __half22float2(h23);
    __half2 l01 = __floats2half2_rn(v.x - f01.x, v.y - f01.y);
    __half2 l23 = __floats2half2_rn(v.z - f23.x, v.w - f23.y);
    *(uint2*)hi = make_uint2(*(uint32_t*)&h01, *(uint32_t*)&h23);
    *(uint2*)lo = make_uint2(*(uint32_t*)&l01, *(uint32_t*)&l23);
}

// ======================= gating =======================
__global__ void gate_kernel(const float* __restrict__ x,
                            const float* __restrict__ Wgate)
{
    __shared__ float sx[H];
    __shared__ float slog[E];
    __shared__ int   s_ids[KSEL];
    __shared__ float s_p[KSEL];

    const int t = blockIdx.x, tid = threadIdx.x;
    for (int i = tid; i < H; i += blockDim.x) sx[i] = x[(size_t)t * H + i];
    __syncthreads();

    const int w = tid >> 5, lane = tid & 31;
    for (int j = 0; j < 8; j++) {
        const int e = w * 8 + j;
        const float* wr = Wgate + (size_t)e * H;
        float s = 0.f;
        for (int h = lane; h < H; h += 32) s += sx[h] * wr[h];
        #pragma unroll
        for (int o = 16; o > 0; o >>= 1) s += __shfl_xor_sync(0xffffffffu, s, o);
        if (lane == 0) slog[e] = s;
    }
    __syncthreads();

    if (tid == 0) {
        float vals[KSEL]; int ids[KSEL];
        for (int j = 0; j < KSEL; j++) {
            float best = -1e30f; int bi = 0;
            for (int e = 0; e < E; e++)
                if (slog[e] > best) { best = slog[e]; bi = e; }
            vals[j] = best; ids[j] = bi; slog[bi] = -1e30f;
        }
        const float m = vals[0];
        float sum = 0.f;
        for (int j = 0; j < KSEL; j++) { vals[j] = expf(vals[j] - m); sum += vals[j]; }
        const float inv = 1.f / sum;
        for (int j = 0; j < KSEL; j++) { s_ids[j] = ids[j]; s_p[j] = vals[j] * inv; }
    }
    __syncthreads();

    if (tid < KSEL) {
        const int e = s_ids[tid];
        const int pos = atomicAdd(&g_cnt[e], 1);
        g_tok[e * T + pos]  = t;
        g_prob[e * T + pos] = s_p[tid];
    }
}

__global__ void scan_kernel()
{
    if (threadIdx.x == 0) {
        int s = 0;
        for (int e = 0; e < E; e++) { g_off[e] = s; s += g_cnt[e]; }
    }
}

// ======================= gate/up: fp16 2-term mma.sync + SwiGLU =======================
// CTA: 64 tokens x 64 i x {Wg,Wu}. 8 warps 2m x 4n, warp 32m x 16i x 2 mats.
__global__ __launch_bounds__(256, 2) void gateup_mma(const float* __restrict__ x,
                                                     const float* __restrict__ Wg,
                                                     const float* __restrict__ Wu)
{
    extern __shared__ __align__(16) char smraw[];
    __half* sm = (__half*)smraw;

    const int e   = blockIdx.z;
    const int cnt = g_cnt[e];
    const int m0  = blockIdx.y * BM;
    if (m0 >= cnt) return;
    const int i0   = blockIdx.x * 64;
    const int base = g_off[e];
    const int tid = threadIdx.x, wid = tid >> 5, lane = tid & 31;

    int*   stok = (int*)(smraw + META_OFF);
    float* sp   = (float*)(smraw + META_OFF + 256);
    if (tid < BM) {
        const int mm = min(m0 + tid, cnt - 1);
        stok[tid] = g_tok[e * T + mm];
        sp[tid]   = (m0 + tid < cnt) ? g_prob[e * T + m0 + tid] : 0.f;
    }
    __syncthreads();

    const float* WgE = Wg + ((size_t)e * II + i0) * H;
    const float* WuE = Wu + ((size_t)e * II + i0) * H;

    const int wm = wid >> 2;   // 0..1
    const int wn = wid & 3;    // 0..3

    const uint32_t offA0 = (uint32_t)((wm * 32 + (lane & 15)) * PADK + ((lane >> 4) << 3));
    const uint32_t offA1 = offA0 + 16 * PADK;
    const uint32_t offB  = (uint32_t)((wn * 16 + ((lane >> 4) << 3) + (lane & 7)) * PADK
                                      + (((lane >> 3) & 1) << 3));

    float ag[2][2][4] = {}, au[2][2][4] = {};
    float4 pa[2], pg[2], pu[2];

    const int NCH = H / BK;    // 64

    // prefetch + fill stage 0
    {
        #pragma unroll
        for (int j = 0; j < 2; j++) {
            const int idx = tid + j * 256, r = idx >> 3, c = idx & 7;
            pa[j] = *(const float4*)(x + (size_t)stok[r] * H + c * 4);
            pg[j] = *(const float4*)(WgE + (size_t)r * H + c * 4);
            pu[j] = *(const float4*)(WuE + (size_t)r * H + c * 4);
        }
        #pragma unroll
        for (int j = 0; j < 2; j++) {
            const int idx = tid + j * 256, off = (idx >> 3) * PADK + (idx & 7) * 4;
            split_sts_f16(sm + GA_HI + off, sm + GA_LO + off, pa[j]);
            *(uint2*)(sm + GG + off) = cvt4_f16(pg[j]);
            *(uint2*)(sm + GU + off) = cvt4_f16(pu[j]);
        }
        __syncthreads();
    }

    for (int ch = 0; ch < NCH; ch++) {
        if (ch + 1 < NCH) {
            const int k0 = (ch + 1) * BK;
            #pragma unroll
            for (int j = 0; j < 2; j++) {
                const int idx = tid + j * 256, r = idx >> 3, c = idx & 7;
                pa[j] = *(const float4*)(x + (size_t)stok[r] * H + k0 + c * 4);
                pg[j] = *(const float4*)(WgE + (size_t)r * H + k0 + c * 4);
                pu[j] = *(const float4*)(WuE + (size_t)r * H + k0 + c * 4);
            }
        }

        // compute on stage ch&1
        {
            const uint32_t sbase = smem_u32(sm + (ch & 1) * STG_ELEMS);
            #pragma unroll
            for (int k16 = 0; k16 < BK; k16 += 16) {
                const uint32_t kb = (uint32_t)k16 * 2;
                uint32_t ah[2][4], al[2][4];
                ldm_x4(ah[0], sbase + (GA_HI * 2) + (offA0 * 2) + kb);
                ldm_x4(al[0], sbase + (GA_LO * 2) + (offA0 * 2) + kb);
                ldm_x4(ah[1], sbase + (GA_HI * 2) + (offA1 * 2) + kb);
                ldm_x4(al[1], sbase + (GA_LO * 2) + (offA1 * 2) + kb);
                uint32_t gv[4], uv[4];
                ldm_x4(gv, sbase + (GG * 2) + (offB * 2) + kb);
                ldm_x4(uv, sbase + (GU * 2) + (offB * 2) + kb);
                #pragma unroll
                for (int mt = 0; mt < 2; mt++) {
                    #pragma unroll
                    for (int it = 0; it < 2; it++) {
                        mma_f16(ag[mt][it], ah[mt], gv[it * 2], gv[it * 2 + 1]);
                        mma_f16(ag[mt][it], al[mt], gv[it * 2], gv[it * 2 + 1]);
                        mma_f16(au[mt][it], ah[mt], uv[it * 2], uv[it * 2 + 1]);
                        mma_f16(au[mt][it], al[mt], uv[it * 2], uv[it * 2 + 1]);
                    }
                }
            }
        }

        if (ch + 1 < NCH) {
            __half* s = sm + ((ch + 1) & 1) * STG_ELEMS;
            #pragma unroll
            for (int j = 0; j < 2; j++) {
                const int idx = tid + j * 256, off = (idx >> 3) * PADK + (idx & 7) * 4;
                split_sts_f16(s + GA_HI + off, s + GA_LO + off, pa[j]);
                *(uint2*)(s + GG + off) = cvt4_f16(pg[j]);
                *(uint2*)(s + GU + off) = cvt4_f16(pu[j]);
            }
        }
        __syncthreads();
    }

    // epilogue: silu(hg)*hu*p -> g_act
    #pragma unroll
    for (int mt = 0; mt < 2; mt++) {
        #pragma unroll
        for (int it = 0; it < 2; it++) {
            const int c  = i0 + wn * 16 + it * 8 + (lane & 3) * 2;
            const int r0 = wm * 32 + mt * 16 + (lane >> 2);
            #pragma unroll
            for (int hf = 0; hf < 2; hf++) {
                const int r = r0 + hf * 8;
                if (m0 + r < cnt) {
                    const float p = sp[r];
                    const float hg0 = ag[mt][it][hf * 2 + 0], hu0 = au[mt][it][hf * 2 + 0];
                    const float hg1 = ag[mt][it][hf * 2 + 1], hu1 = au[mt][it][hf * 2 + 1];
                    float2 v;
                    v.x = hg0 / (1.f + expf(-hg0)) * hu0 * p;
                    v.y = hg1 / (1.f + expf(-hg1)) * hu1 * p;
                    *(float2*)(g_act + (size_t)(base + m0 + r) * II + c) = v;
                }
            }
        }
    }
}

// ======================= down: fp16 2-term mma.sync + scatter =======================
// CTA: 64 rows x 128 h-cols. 8 warps 2m x 4n, warp 32m x 32n.
__global__ __launch_bounds__(256, 2) void down_mma(const float* __restrict__ Wd,
                                                   float* __restrict__ out)
{
    extern __shared__ __align__(16) char smraw[];
    __half* sm = (__half*)smraw;

    const int e   = blockIdx.z;
    const int cnt = g_cnt[e];
    const int m0  = blockIdx.y * BM;
    if (m0 >= cnt) return;
    const int n0   = blockIdx.x * 128;
    const int base = g_off[e];
    const int tid = threadIdx.x, wid = tid >> 5, lane = tid & 31;

    int* stok = (int*)(smraw + META_OFF);
    int* srow = (int*)(smraw + META_OFF + 256);
    if (tid < BM) {
        const int mm = min(m0 + tid, cnt - 1);
        stok[tid] = g_tok[e * T + mm];
        srow[tid] = base + mm;
    }
    __syncthreads();

    const float* WdE = Wd + ((size_t)e * H + n0) * II;

    const int wm = wid >> 2;   // 0..1
    const int wn = wid & 3;    // 0..3

    const uint32_t offA0 = (uint32_t)((wm * 32 + (lane & 15)) * PADK + ((lane >> 4) << 3));
    const uint32_t offA1 = offA0 + 16 * PADK;
    const uint32_t offB0 = (uint32_t)((wn * 32 + ((lane >> 4) << 3) + (lane & 7)) * PADK
                                      + (((lane >> 3) & 1) << 3));
    const uint32_t offB1 = offB0 + 16 * PADK;

    float acc[2][4][4] = {};
    float4 pa[2], pb[4];

    const int NCH = II / BK;   // 32

    {
        #pragma unroll
        for (int j = 0; j < 2; j++) {
            const int idx = tid + j * 256, r = idx >> 3, c = idx & 7;
            pa[j] = *(const float4*)(g_act + (size_t)srow[r] * II + c * 4);
        }
        #pragma unroll
        for (int j = 0; j < 4; j++) {
            const int idx = tid + j * 256, r = idx >> 3, c = idx & 7;
            pb[j] = *(const float4*)(WdE + (size_t)r * II + c * 4);
        }
        #pragma unroll
        for (int j = 0; j < 2; j++) {
            const int idx = tid + j * 256, off = (idx >> 3) * PADK + (idx & 7) * 4;
            split_sts_f16(sm + DA_HI + off, sm + DA_LO + off, pa[j]);
        }
        #pragma unroll
        for (int j = 0; j < 4; j++) {
            const int idx = tid + j * 256, off = (idx >> 3) * PADK + (idx & 7) * 4;
            *(uint2*)(sm + DB + off) = cvt4_f16(pb[j]);
        }
        __syncthreads();
    }

    for (int ch = 0; ch < NCH; ch++) {
        if (ch + 1 < NCH) {
            const int k0 = (ch + 1) * BK;
            #pragma unroll
            for (int j = 0; j < 2; j++) {
                const int idx = tid + j * 256, r = idx >> 3, c = idx & 7;
                pa[j] = *(const float4*)(g_act + (size_t)srow[r] * II + k0 + c * 4);
            }
            #pragma unroll
            for (int j = 0; j < 4; j++) {
                const int idx = tid + j * 256, r = idx >> 3, c = idx & 7;
                pb[j] = *(const float4*)(WdE + (size_t)r * II + k0 + c * 4);
            }
        }

        {
            const uint32_t sbase = smem_u32(sm + (ch & 1) * STG_ELEMS);
            #pragma unroll
            for (int k16 = 0; k16 < BK; k16 += 16) {
                const uint32_t kb = (uint32_t)k16 * 2;
                uint32_t ah[2][4], al[2][4];
                ldm_x4(ah[0], sbase + (DA_HI * 2) + (offA0 * 2) + kb);
                ldm_x4(al[0], sbase + (DA_LO * 2) + (offA0 * 2) + kb);
                ldm_x4(ah[1], sbase + (DA_HI * 2) + (offA1 * 2) + kb);
                ldm_x4(al[1], sbase + (DA_LO * 2) + (offA1 * 2) + kb);
                uint32_t bv[2][4];
                ldm_x4(bv[0], sbase + (DB * 2) + (offB0 * 2) + kb);
                ldm_x4(bv[1], sbase + (DB * 2) + (offB1 * 2) + kb);
                #pragma unroll
                for (int mt = 0; mt < 2; mt++) {
                    #pragma unroll
                    for (int nt = 0; nt < 4; nt++) {
                        const int p = nt >> 1, q = (nt & 1) * 2;
                        mma_f16(acc[mt][nt], ah[mt], bv[p][q], bv[p][q + 1]);
                        mma_f16(acc[mt][nt], al[mt], bv[p][q], bv[p][q + 1]);
                    }
                }
            }
        }

        if (ch + 1 < NCH) {
            __half* s = sm + ((ch + 1) & 1) * STG_ELEMS;
            #pragma unroll
            for (int j = 0; j < 2; j++) {
                const int idx = tid + j * 256, off = (idx >> 3) * PADK + (idx & 7) * 4;
                split_sts_f16(s + DA_HI + off, s + DA_LO + off, pa[j]);
            }
            #pragma unroll
            for (int j = 0; j < 4; j++) {
                const int idx = tid + j * 256, off = (idx >> 3) * PADK + (idx & 7) * 4;
                *(uint2*)(s + DB + off) = cvt4_f16(pb[j]);
            }
        }
        __syncthreads();
    }

    // epilogue: atomic scatter into out
    #pragma unroll
    for (int mt = 0; mt < 2; mt++) {
        #pragma unroll
        for (int nt = 0; nt < 4; nt++) {
            const int c  = n0 + wn * 32 + nt * 8 + (lane & 3) * 2;
            const int r0 = wm * 32 + mt * 16 + (lane >> 2);
            #pragma unroll
            for (int hf = 0; hf < 2; hf++) {
                const int r = r0 + hf * 8;
                if (m0 + r < cnt) {
                    float* orow = out + (size_t)stok[r] * H + c;
                    atomicAdd(&orow[0], acc[mt][nt][hf * 2 + 0]);
                    atomicAdd(&orow[1], acc[mt][nt][hf * 2 + 1]);
                }
            }
        }
    }
}

// ======================= launch =======================
extern "C" void kernel_launch(void* const* d_in, const int* in_sizes, int n_in,
                              void* d_out, int out_size)
{
    const float* x     = (const float*)d_in[0];
    const float* Wg    = (const float*)d_in[1];
    const float* Wu    = (const float*)d_in[2];
    const float* Wd    = (const float*)d_in[3];
    const float* Wgate = (const float*)d_in[4];
    float* out = (float*)d_out;

    cudaFuncSetAttribute(gateup_mma, cudaFuncAttributeMaxDynamicSharedMemorySize, SMEM_DYN);
    cudaFuncSetAttribute(down_mma,   cudaFuncAttributeMaxDynamicSharedMemorySize, SMEM_DYN);

    void* cnt_ptr = nullptr;
    cudaGetSymbolAddress(&cnt_ptr, g_cnt);
    cudaMemsetAsync(cnt_ptr, 0, E * sizeof(int));
    cudaMemsetAsync(d_out, 0, (size_t)T * H * sizeof(float));

    gate_kernel<<<T, 256>>>(x, Wgate);
    scan_kernel<<<1, 32>>>();

    dim3 g1(II / 64, T / BM, E);     // 16 x 8 x 64
    gateup_mma<<<g1, 256, SMEM_DYN>>>(x, Wg, Wu);

    dim3 g2(H / 128, T / BM, E);     // 16 x 8 x 64
    down_mma<<<g2, 256, SMEM_DYN>>>(Wd, out);
}

// round 13
// speedup vs baseline: 1.5603x; 1.0644x over previous
#include <cuda_runtime.h>
#include <cuda_fp16.h>
#include <stdint.h>
#include <math.h>

#define T    512
#define H    2048
#define II   1024
#define E    64
#define KSEL 8

#define BM   64
#define BK   32
#define PADK 40                      // padded k-stride (fp16 elems): 80B, ldmatrix conflict-free

// stage = 7680 fp16 elems = 15360 B; two stages.
#define STG_ELEMS 7680
#define META_OFF  (2 * STG_ELEMS * 2)          // 30720 B
#define SMEM_DYN  (META_OFF + 1024)

// gateup regions (elem offsets within a stage): A 64x40, G 64x40, U 64x40
#define GA 0
#define GG 2560
#define GU 5120
// down regions: A 64x40, B 128x40
#define DA 0
#define DB 2560

// -------- device-global scratch (no allocations allowed) --------
__device__ int    g_cnt[E];
__device__ int    g_off[E];
__device__ int    g_tok[E * T];
__device__ float  g_prob[E * T];
__device__ __half g_act[(size_t)T * KSEL * II];   // activations stored fp16

// ======================= helpers =======================
__device__ __forceinline__ uint32_t smem_u32(const void* p) {
    uint32_t a;
    asm("{ .reg .u64 t; cvta.to.shared.u64 t, %1; cvt.u32.u64 %0, t; }" : "=r"(a) : "l"(p));
    return a;
}

__device__ __forceinline__ void ldm_x4(uint32_t r[4], uint32_t addr) {
    asm volatile("ldmatrix.sync.aligned.m8n8.x4.shared.b16 {%0,%1,%2,%3}, [%4];"
                 : "=r"(r[0]), "=r"(r[1]), "=r"(r[2]), "=r"(r[3]) : "r"(addr));
}
__device__ __forceinline__ void mma_f16(float d[4], const uint32_t a[4], uint32_t b0, uint32_t b1) {
    asm volatile("mma.sync.aligned.m16n8k16.row.col.f32.f16.f16.f32 "
                 "{%0,%1,%2,%3}, {%4,%5,%6,%7}, {%8,%9}, {%0,%1,%2,%3};"
                 : "+f"(d[0]), "+f"(d[1]), "+f"(d[2]), "+f"(d[3])
                 : "r"(a[0]), "r"(a[1]), "r"(a[2]), "r"(a[3]), "r"(b0), "r"(b1));
}

// fp32x4 -> fp16x4 single plane (8 B)
__device__ __forceinline__ uint2 cvt4_f16(float4 v) {
    __half2 a = __floats2half2_rn(v.x, v.y);
    __half2 b = __floats2half2_rn(v.z, v.w);
    uint2 r;
    r.x = *(uint32_t*)&a;
    r.y = *(uint32_t*)&b;
    return r;
}

// ======================= gating =======================
__global__ void gate_kernel(const float* __restrict__ x,
                            const float* __restrict__ Wgate)
{
    __shared__ float sx[H];
    __shared__ float slog[E];
    __shared__ int   s_ids[KSEL];
    __shared__ float s_p[KSEL];

    const int t = blockIdx.x, tid = threadIdx.x;
    for (int i = tid; i < H; i += blockDim.x) sx[i] = x[(size_t)t * H + i];
    __syncthreads();

    const int w = tid >> 5, lane = tid & 31;
    for (int j = 0; j < 8; j++) {
        const int e = w * 8 + j;
        const float* wr = Wgate + (size_t)e * H;
        float s = 0.f;
        for (int h = lane; h < H; h += 32) s += sx[h] * wr[h];
        #pragma unroll
        for (int o = 16; o > 0; o >>= 1) s += __shfl_xor_sync(0xffffffffu, s, o);
        if (lane == 0) slog[e] = s;
    }
    __syncthreads();

    if (tid == 0) {
        float vals[KSEL]; int ids[KSEL];
        for (int j = 0; j < KSEL; j++) {
            float best = -1e30f; int bi = 0;
            for (int e = 0; e < E; e++)
                if (slog[e] > best) { best = slog[e]; bi = e; }
            vals[j] = best; ids[j] = bi; slog[bi] = -1e30f;
        }
        const float m = vals[0];
        float sum = 0.f;
        for (int j = 0; j < KSEL; j++) { vals[j] = expf(vals[j] - m); sum += vals[j]; }
        const float inv = 1.f / sum;
        for (int j = 0; j < KSEL; j++) { s_ids[j] = ids[j]; s_p[j] = vals[j] * inv; }
    }
    __syncthreads();

    if (tid < KSEL) {
        const int e = s_ids[tid];
        const int pos = atomicAdd(&g_cnt[e], 1);
        g_tok[e * T + pos]  = t;
        g_prob[e * T + pos] = s_p[tid];
    }
}

__global__ void scan_kernel()
{
    if (threadIdx.x == 0) {
        int s = 0;
        for (int e = 0; e < E; e++) { g_off[e] = s; s += g_cnt[e]; }
    }
}

// ======================= gate/up: fp16 mma.sync + SwiGLU =======================
// CTA: 64 tokens x 64 i x {Wg,Wu}. 8 warps 2m x 4n, warp 32m x 16i x 2 mats.
__global__ __launch_bounds__(256, 2) void gateup_mma(const float* __restrict__ x,
                                                     const float* __restrict__ Wg,
                                                     const float* __restrict__ Wu)
{
    extern __shared__ __align__(16) char smraw[];
    __half* sm = (__half*)smraw;

    const int e   = blockIdx.z;
    const int cnt = g_cnt[e];
    const int m0  = blockIdx.y * BM;
    if (m0 >= cnt) return;
    const int i0   = blockIdx.x * 64;
    const int base = g_off[e];
    const int tid = threadIdx.x, wid = tid >> 5, lane = tid & 31;

    int*   stok = (int*)(smraw + META_OFF);
    float* sp   = (float*)(smraw + META_OFF + 256);
    if (tid < BM) {
        const int mm = min(m0 + tid, cnt - 1);
        stok[tid] = g_tok[e * T + mm];
        sp[tid]   = (m0 + tid < cnt) ? g_prob[e * T + m0 + tid] : 0.f;
    }
    __syncthreads();

    const float* WgE = Wg + ((size_t)e * II + i0) * H;
    const float* WuE = Wu + ((size_t)e * II + i0) * H;

    const int wm = wid >> 2;   // 0..1
    const int wn = wid & 3;    // 0..3

    const uint32_t offA0 = (uint32_t)((wm * 32 + (lane & 15)) * PADK + ((lane >> 4) << 3));
    const uint32_t offA1 = offA0 + 16 * PADK;
    const uint32_t offB  = (uint32_t)((wn * 16 + ((lane >> 4) << 3) + (lane & 7)) * PADK
                                      + (((lane >> 3) & 1) << 3));

    float ag[2][2][4] = {}, au[2][2][4] = {};
    float4 pa[2], pg[2], pu[2];

    const int NCH = H / BK;    // 64

    // prefetch + fill stage 0
    {
        #pragma unroll
        for (int j = 0; j < 2; j++) {
            const int idx = tid + j * 256, r = idx >> 3, c = idx & 7;
            pa[j] = *(const float4*)(x + (size_t)stok[r] * H + c * 4);
            pg[j] = *(const float4*)(WgE + (size_t)r * H + c * 4);
            pu[j] = *(const float4*)(WuE + (size_t)r * H + c * 4);
        }
        #pragma unroll
        for (int j = 0; j < 2; j++) {
            const int idx = tid + j * 256, off = (idx >> 3) * PADK + (idx & 7) * 4;
            *(uint2*)(sm + GA + off) = cvt4_f16(pa[j]);
            *(uint2*)(sm + GG + off) = cvt4_f16(pg[j]);
            *(uint2*)(sm + GU + off) = cvt4_f16(pu[j]);
        }
        __syncthreads();
    }

    for (int ch = 0; ch < NCH; ch++) {
        if (ch + 1 < NCH) {
            const int k0 = (ch + 1) * BK;
            #pragma unroll
            for (int j = 0; j < 2; j++) {
                const int idx = tid + j * 256, r = idx >> 3, c = idx & 7;
                pa[j] = *(const float4*)(x + (size_t)stok[r] * H + k0 + c * 4);
                pg[j] = *(const float4*)(WgE + (size_t)r * H + k0 + c * 4);
                pu[j] = *(const float4*)(WuE + (size_t)r * H + k0 + c * 4);
            }
        }

        // compute on stage ch&1
        {
            const uint32_t sbase = smem_u32(sm + (ch & 1) * STG_ELEMS);
            #pragma unroll
            for (int k16 = 0; k16 < BK; k16 += 16) {
                const uint32_t kb = (uint32_t)k16 * 2;
                uint32_t ah[2][4];
                ldm_x4(ah[0], sbase + (GA * 2) + (offA0 * 2) + kb);
                ldm_x4(ah[1], sbase + (GA * 2) + (offA1 * 2) + kb);
                uint32_t gv[4], uv[4];
                ldm_x4(gv, sbase + (GG * 2) + (offB * 2) + kb);
                ldm_x4(uv, sbase + (GU * 2) + (offB * 2) + kb);
                #pragma unroll
                for (int mt = 0; mt < 2; mt++) {
                    #pragma unroll
                    for (int it = 0; it < 2; it++) {
                        mma_f16(ag[mt][it], ah[mt], gv[it * 2], gv[it * 2 + 1]);
                        mma_f16(au[mt][it], ah[mt], uv[it * 2], uv[it * 2 + 1]);
                    }
                }
            }
        }

        if (ch + 1 < NCH) {
            __half* s = sm + ((ch + 1) & 1) * STG_ELEMS;
            #pragma unroll
            for (int j = 0; j < 2; j++) {
                const int idx = tid + j * 256, off = (idx >> 3) * PADK + (idx & 7) * 4;
                *(uint2*)(s + GA + off) = cvt4_f16(pa[j]);
                *(uint2*)(s + GG + off) = cvt4_f16(pg[j]);
                *(uint2*)(s + GU + off) = cvt4_f16(pu[j]);
            }
        }
        __syncthreads();
    }

    // epilogue: silu(hg)*hu*p -> g_act (fp16)
    #pragma unroll
    for (int mt = 0; mt < 2; mt++) {
        #pragma unroll
        for (int it = 0; it < 2; it++) {
            const int c  = i0 + wn * 16 + it * 8 + (lane & 3) * 2;
            const int r0 = wm * 32 + mt * 16 + (lane >> 2);
            #pragma unroll
            for (int hf = 0; hf < 2; hf++) {
                const int r = r0 + hf * 8;
                if (m0 + r < cnt) {
                    const float p = sp[r];
                    const float hg0 = ag[mt][it][hf * 2 + 0], hu0 = au[mt][it][hf * 2 + 0];
                    const float hg1 = ag[mt][it][hf * 2 + 1], hu1 = au[mt][it][hf * 2 + 1];
                    const float v0 = hg0 / (1.f + expf(-hg0)) * hu0 * p;
                    const float v1 = hg1 / (1.f + expf(-hg1)) * hu1 * p;
                    __half2 hv = __floats2half2_rn(v0, v1);
                    *(uint32_t*)(g_act + (size_t)(base + m0 + r) * II + c) = *(uint32_t*)&hv;
                }
            }
        }
    }
}

// ======================= down: fp16 mma.sync + scatter =======================
// CTA: 64 rows x 128 h-cols. 8 warps 2m x 4n, warp 32m x 32n.
__global__ __launch_bounds__(256, 2) void down_mma(const float* __restrict__ Wd,
                                                   float* __restrict__ out)
{
    extern __shared__ __align__(16) char smraw[];
    __half* sm = (__half*)smraw;

    const int e   = blockIdx.z;
    const int cnt = g_cnt[e];
    const int m0  = blockIdx.y * BM;
    if (m0 >= cnt) return;
    const int n0   = blockIdx.x * 128;
    const int base = g_off[e];
    const int tid = threadIdx.x, wid = tid >> 5, lane = tid & 31;

    int* stok = (int*)(smraw + META_OFF);
    int* srow = (int*)(smraw + META_OFF + 256);
    if (tid < BM) {
        const int mm = min(m0 + tid, cnt - 1);
        stok[tid] = g_tok[e * T + mm];
        srow[tid] = base + mm;
    }
    __syncthreads();

    const float* WdE = Wd + ((size_t)e * H + n0) * II;

    const int wm = wid >> 2;   // 0..1
    const int wn = wid & 3;    // 0..3

    const uint32_t offA0 = (uint32_t)((wm * 32 + (lane & 15)) * PADK + ((lane >> 4) << 3));
    const uint32_t offA1 = offA0 + 16 * PADK;
    const uint32_t offB0 = (uint32_t)((wn * 32 + ((lane >> 4) << 3) + (lane & 7)) * PADK
                                      + (((lane >> 3) & 1) << 3));
    const uint32_t offB1 = offB0 + 16 * PADK;

    float acc[2][4][4] = {};
    uint4  pa;                 // 8 fp16 of A per thread
    float4 pb[4];

    // producer geometry: A fp16 64 rows x 32 k = 256 x 16B tasks
    const int ra  = tid >> 2;            // 0..63
    const int sga = (tid & 3) * 8;       // fp16 elem offset within chunk
    const __half* srcA = g_act;          // + srow[ra]*II + k0 + sga
    const uint32_t dstA = (uint32_t)(ra * PADK + sga);

    const int NCH = II / BK;   // 32

    {
        pa = *(const uint4*)(g_act + (size_t)srow[ra] * II + sga);
        #pragma unroll
        for (int j = 0; j < 4; j++) {
            const int idx = tid + j * 256, r = idx >> 3, c = idx & 7;
            pb[j] = *(const float4*)(WdE + (size_t)r * II + c * 4);
        }
        *(uint4*)(sm + DA + dstA) = pa;
        #pragma unroll
        for (int j = 0; j < 4; j++) {
            const int idx = tid + j * 256, off = (idx >> 3) * PADK + (idx & 7) * 4;
            *(uint2*)(sm + DB + off) = cvt4_f16(pb[j]);
        }
        __syncthreads();
    }

    for (int ch = 0; ch < NCH; ch++) {
        if (ch + 1 < NCH) {
            const int k0 = (ch + 1) * BK;
            pa = *(const uint4*)(g_act + (size_t)srow[ra] * II + k0 + sga);
            #pragma unroll
            for (int j = 0; j < 4; j++) {
                const int idx = tid + j * 256, r = idx >> 3, c = idx & 7;
                pb[j] = *(const float4*)(WdE + (size_t)r * II + k0 + c * 4);
            }
        }

        {
            const uint32_t sbase = smem_u32(sm + (ch & 1) * STG_ELEMS);
            #pragma unroll
            for (int k16 = 0; k16 < BK; k16 += 16) {
                const uint32_t kb = (uint32_t)k16 * 2;
                uint32_t ah[2][4];
                ldm_x4(ah[0], sbase + (DA * 2) + (offA0 * 2) + kb);
                ldm_x4(ah[1], sbase + (DA * 2) + (offA1 * 2) + kb);
                uint32_t bv[2][4];
                ldm_x4(bv[0], sbase + (DB * 2) + (offB0 * 2) + kb);
                ldm_x4(bv[1], sbase + (DB * 2) + (offB1 * 2) + kb);
                #pragma unroll
                for (int mt = 0; mt < 2; mt++) {
                    #pragma unroll
                    for (int nt = 0; nt < 4; nt++) {
                        const int p = nt >> 1, q = (nt & 1) * 2;
                        mma_f16(acc[mt][nt], ah[mt], bv[p][q], bv[p][q + 1]);
                    }
                }
            }
        }

        if (ch + 1 < NCH) {
            __half* s = sm + ((ch + 1) & 1) * STG_ELEMS;
            *(uint4*)(s + DA + dstA) = pa;
            #pragma unroll
            for (int j = 0; j < 4; j++) {
                const int idx = tid + j * 256, off = (idx >> 3) * PADK + (idx & 7) * 4;
                *(uint2*)(s + DB + off) = cvt4_f16(pb[j]);
            }
        }
        __syncthreads();
    }

    // epilogue: atomic scatter into out
    #pragma unroll
    for (int mt = 0; mt < 2; mt++) {
        #pragma unroll
        for (int nt = 0; nt < 4; nt++) {
            const int c  = n0 + wn * 32 + nt * 8 + (lane & 3) * 2;
            const int r0 = wm * 32 + mt * 16 + (lane >> 2);
            #pragma unroll
            for (int hf = 0; hf < 2; hf++) {
                const int r = r0 + hf * 8;
                if (m0 + r < cnt) {
                    float* orow = out + (size_t)stok[r] * H + c;
                    atomicAdd(&orow[0], acc[mt][nt][hf * 2 + 0]);
                    atomicAdd(&orow[1], acc[mt][nt][hf * 2 + 1]);
                }
            }
        }
    }
}

// ======================= launch =======================
extern "C" void kernel_launch(void* const* d_in, const int* in_sizes, int n_in,
                              void* d_out, int out_size)
{
    const float* x     = (const float*)d_in[0];
    const float* Wg    = (const float*)d_in[1];
    const float* Wu    = (const float*)d_in[2];
    const float* Wd    = (const float*)d_in[3];
    const float* Wgate = (const float*)d_in[4];
    float* out = (float*)d_out;

    cudaFuncSetAttribute(gateup_mma, cudaFuncAttributeMaxDynamicSharedMemorySize, SMEM_DYN);
    cudaFuncSetAttribute(down_mma,   cudaFuncAttributeMaxDynamicSharedMemorySize, SMEM_DYN);

    void* cnt_ptr = nullptr;
    cudaGetSymbolAddress(&cnt_ptr, g_cnt);
    cudaMemsetAsync(cnt_ptr, 0, E * sizeof(int));
    cudaMemsetAsync(d_out, 0, (size_t)T * H * sizeof(float));

    gate_kernel<<<T, 256>>>(x, Wgate);
    scan_kernel<<<1, 32>>>();

    dim3 g1(II / 64, T / BM, E);     // 16 x 8 x 64
    gateup_mma<<<g1, 256, SMEM_DYN>>>(x, Wg, Wu);

    dim3 g2(H / 128, T / BM, E);     // 16 x 8 x 64
    down_mma<<<g2, 256, SMEM_DYN>>>(Wd, out);
}